// round 6
// baseline (speedup 1.0000x reference)
#include <cuda_runtime.h>

// Problem constants
#define CC   256     // input channels
#define CR   64      // bottleneck channels
#define HH   56
#define WW   56
#define BB   4
#define GG   16      // groups
#define CGC  16      // channels per group
#define KK   7
#define NPIX (HH*WW)     // 3136
#define NQ   (BB*NPIX)   // 12544

// Scratch for the bottleneck activations, pixel-major: t_buf[q*64 + c]
__device__ float t_buf[NQ * CR];

// ---------------- packed f32x2 helpers ----------------
__device__ __forceinline__ unsigned long long ffma2(unsigned long long a,
                                                    unsigned long long b,
                                                    unsigned long long c) {
    unsigned long long d;
    asm("fma.rn.f32x2 %0, %1, %2, %3;" : "=l"(d) : "l"(a), "l"(b), "l"(c));
    return d;
}
__device__ __forceinline__ float2 u2f(unsigned long long v) {
    float2 r;
    asm("mov.b64 {%0,%1}, %2;" : "=f"(r.x), "=f"(r.y) : "l"(v));
    return r;
}
__device__ __forceinline__ unsigned long long f2u(float x, float y) {
    unsigned long long v;
    asm("mov.b64 %0, {%1,%2};" : "=l"(v) : "f"(x), "f"(y));
    return v;
}

// =====================================================================
// Kernel 1: t = relu(BN(x @ W1^T + b1)), stored pixel-major t_buf[q][64]
// Grid: 196 CTAs x 256 threads. Thread = (o-quarter, pixel).
// =====================================================================
#define W1T_STRIDE 66   // padded stride: keeps float2 loads 8B-aligned, spreads banks

extern "C" __global__ void __launch_bounds__(256)
k1_gen_t(const float* __restrict__ x, const float* __restrict__ W1,
         const float* __restrict__ b1, const float* __restrict__ gamma,
         const float* __restrict__ beta, const float* __restrict__ mean,
         const float* __restrict__ var)
{
    extern __shared__ float sm1[];
    float* w1T = sm1;                         // [256][66]
    float* sc  = sm1 + CC * W1T_STRIDE;       // [64]
    float* sh  = sc + CR;                     // [64]

    int tid = threadIdx.x;

    // Load W1 (Cr=64 x C=256, row-major) transposed into smem: w1T[c][o].
    // i enumerates (o,c) so global reads are coalesced.
    for (int i = tid; i < CR * CC; i += 256) {
        int o = i >> 8;        // i / 256
        int c = i & 255;       // i % 256
        w1T[c * W1T_STRIDE + o] = W1[i];
    }
    if (tid < CR) {
        float s = gamma[tid] * rsqrtf(var[tid] + 1e-5f);
        sc[tid] = s;
        sh[tid] = (b1[tid] - mean[tid]) * s + beta[tid];
    }
    __syncthreads();

    int oq = tid >> 6;                 // 0..3 -> which 16 outputs
    int p  = tid & 63;
    int q  = blockIdx.x * 64 + p;      // global pixel id, 0..12543 (exact)
    int b  = q / NPIX;
    int hw = q - b * NPIX;
    const float* xp = x + (size_t)b * (CC * NPIX) + hw;
    int o0 = oq * 16;

    unsigned long long acc[8];
    #pragma unroll
    for (int m = 0; m < 8; m++) acc[m] = 0ull;

    for (int c = 0; c < CC; c++) {
        float xv = xp[c * NPIX];                       // coalesced across lanes
        unsigned long long xx = f2u(xv, xv);
        const unsigned long long* wrow =
            (const unsigned long long*)(w1T + c * W1T_STRIDE + o0);
        #pragma unroll
        for (int m = 0; m < 8; m++)
            acc[m] = ffma2(xx, wrow[m], acc[m]);       // broadcast LDS.64 + FFMA2
    }

    float* tb = t_buf + (size_t)q * CR + o0;
    #pragma unroll
    for (int m = 0; m < 8; m++) {
        float2 v = u2f(acc[m]);
        int o = o0 + 2 * m;
        float a0 = fmaxf(v.x * sc[o]     + sh[o],     0.f);
        float a1 = fmaxf(v.y * sc[o + 1] + sh[o + 1], 0.f);
        *(float2*)(tb + 2 * m) = make_float2(a0, a1);
    }
}

// =====================================================================
// Kernel 2 (fused): per-pixel kernel generation (GEMM2) + involution.
// Grid: (14 row-tiles, 16 groups, 4 batches), 256 threads.
// Thread t<224 owns pixel (rl=t/56, cl=t%56) in a 4x56 strip:
//   - holds t[64] in registers (32 f32x2)
//   - computes its 49 kernel weights -> smem strip (conflict-free stride 49)
//   - accumulates 16-channel x 49-tap involution from padded x tile in smem
// =====================================================================
#define XT_W 62          // 56 + 2*3
#define XT_H 10          // 4  + 2*3
#define XT_CH (XT_H*XT_W)    // 620 floats per channel

extern "C" __global__ void __launch_bounds__(256)
k2_inv(const float* __restrict__ x, const float* __restrict__ W2,
       const float* __restrict__ b2, float* __restrict__ out)
{
    extern __shared__ float sm2[];
    float* xs  = sm2;                    // [16][10][62] = 9920
    float* w2s = xs + CGC * XT_CH;       // [49][64]     = 3136
    float* b2s = w2s + 49 * CR;          // [64] (49 used)
    float* ws  = b2s + 64;               // [224][49]    = 10976

    int tid = threadIdx.x;
    int r0  = blockIdx.x * 4;
    int g   = blockIdx.y;
    int b   = blockIdx.z;

    // ---- cooperative loads ----
    const float* xg = x + (size_t)((b * GG + g) * CGC) * NPIX;
    for (int i = tid; i < CGC * XT_CH; i += 256) {
        int cg  = i / XT_CH;
        int rem = i - cg * XT_CH;
        int ri  = rem / XT_W;
        int ci  = rem - ri * XT_W;
        int gr  = r0 - 3 + ri;
        int gc  = ci - 3;
        float v = 0.f;
        if ((unsigned)gr < HH && (unsigned)gc < WW)
            v = xg[cg * NPIX + gr * WW + gc];
        xs[i] = v;
    }
    for (int i = tid; i < 49 * CR; i += 256)
        w2s[i] = W2[(size_t)g * 49 * CR + i];
    if (tid < 49) b2s[tid] = b2[g * 49 + tid];

    // thread-private t vector in registers (packed f32x2)
    unsigned long long tt[32];
    int rl = tid / WW;
    int cl = tid - rl * WW;
    if (tid < 224) {
        int q = b * NPIX + (r0 + rl) * WW + cl;
        const float4* ts = (const float4*)(t_buf + (size_t)q * CR);
        #pragma unroll
        for (int m = 0; m < 16; m++) {
            float4 v = ts[m];
            tt[2 * m]     = f2u(v.x, v.y);
            tt[2 * m + 1] = f2u(v.z, v.w);
        }
    }
    __syncthreads();

    if (tid >= 224) return;

    // ---- kernel generation: w[k] = t . W2[g*49+k] + b2 ----
    float* wsp = ws + tid * 49;          // stride 49 -> bank pattern 17*lane: conflict-free
    for (int k = 0; k < 49; k++) {
        const unsigned long long* w2row =
            (const unsigned long long*)(w2s + k * CR);   // uniform -> broadcast LDS
        unsigned long long acc = 0ull;
        #pragma unroll
        for (int c2 = 0; c2 < 32; c2++)
            acc = ffma2(tt[c2], w2row[c2], acc);
        float2 u = u2f(acc);
        wsp[k] = u.x + u.y + b2s[k];
    }

    // ---- involution: out[cg] = sum_k xs[cg][rl+i][cl+j] * w[i*7+j] ----
    float a[16];
    #pragma unroll
    for (int cg = 0; cg < 16; cg++) a[cg] = 0.f;

    const float* xbase = xs + rl * XT_W + cl;
    for (int i = 0; i < KK; i++) {
        const float* xrow = xbase + i * XT_W;
        const float* wrow = wsp + i * KK;
        #pragma unroll
        for (int j = 0; j < KK; j++) {
            float wv = wrow[j];
            #pragma unroll
            for (int cg = 0; cg < 16; cg++)
                a[cg] += xrow[cg * XT_CH + j] * wv;
        }
    }

    float* op = out + (size_t)(b * CC + g * CGC) * NPIX + (r0 + rl) * WW + cl;
    #pragma unroll
    for (int cg = 0; cg < 16; cg++)
        op[cg * NPIX] = a[cg];
}

// =====================================================================
// Launch
// =====================================================================
extern "C" void kernel_launch(void* const* d_in, const int* in_sizes, int n_in,
                              void* d_out, int out_size) {
    const float* x     = (const float*)d_in[0];
    const float* W1    = (const float*)d_in[1];
    const float* b1    = (const float*)d_in[2];
    const float* gamma = (const float*)d_in[3];
    const float* beta  = (const float*)d_in[4];
    const float* mean  = (const float*)d_in[5];
    const float* var   = (const float*)d_in[6];
    const float* W2    = (const float*)d_in[7];
    const float* b2    = (const float*)d_in[8];
    float* out = (float*)d_out;

    const int smem1 = (CC * W1T_STRIDE + 2 * CR) * sizeof(float);              // ~68 KB
    const int smem2 = (CGC * XT_CH + 49 * CR + 64 + 224 * 49) * sizeof(float); // ~96 KB

    (void)cudaFuncSetAttribute(k1_gen_t, cudaFuncAttributeMaxDynamicSharedMemorySize, smem1);
    (void)cudaFuncSetAttribute(k2_inv,   cudaFuncAttributeMaxDynamicSharedMemorySize, smem2);

    k1_gen_t<<<NQ / 64, 256, smem1>>>(x, W1, b1, gamma, beta, mean, var);
    k2_inv<<<dim3(HH / 4, GG, BB), 256, smem2>>>(x, W2, b2, out);
}

// round 7
// speedup vs baseline: 1.2135x; 1.2135x over previous
#include <cuda_runtime.h>

// Problem constants
#define CC   256
#define CR   64
#define HH   56
#define WW   56
#define BB   4
#define GG   16
#define CGC  16
#define KK   7
#define NPIX (HH*WW)     // 3136
#define NQ   (BB*NPIX)   // 12544

// Bottleneck activations, channel-pair-major: t2_buf[c2*NQ + q] = (t[2c2], t[2c2+1])
__device__ unsigned long long t2_buf[32 * NQ];

// ---------------- packed f32x2 helpers ----------------
__device__ __forceinline__ unsigned long long ffma2(unsigned long long a,
                                                    unsigned long long b,
                                                    unsigned long long c) {
    unsigned long long d;
    asm("fma.rn.f32x2 %0, %1, %2, %3;" : "=l"(d) : "l"(a), "l"(b), "l"(c));
    return d;
}
__device__ __forceinline__ float2 u2f(unsigned long long v) {
    float2 r;
    asm("mov.b64 {%0,%1}, %2;" : "=f"(r.x), "=f"(r.y) : "l"(v));
    return r;
}
__device__ __forceinline__ unsigned long long f2u(float x, float y) {
    unsigned long long v;
    asm("mov.b64 %0, {%1,%2};" : "=l"(v) : "f"(x), "f"(y));
    return v;
}

// =====================================================================
// Kernel 1: t = relu(BN(x @ W1^T + b1)) -> t2_buf[c2][q]
// 196 CTAs x 128 threads. Thread = (oq = tid>>5, lane s): 2 pixels (q, q+32),
// 16 outputs. Broadcast weights via LDS.128, amortized over 2 pixels.
// =====================================================================
#define W1T_STRIDE 68   // floats; 68*4 bytes per row -> every (c,o0) float4 16B-aligned

extern "C" __global__ void __launch_bounds__(128)
k1_gen_t(const float* __restrict__ x, const float* __restrict__ W1,
         const float* __restrict__ b1, const float* __restrict__ gamma,
         const float* __restrict__ beta, const float* __restrict__ mean,
         const float* __restrict__ var)
{
    extern __shared__ float sm1[];
    float* w1T = sm1;                         // [256][68]
    float* sc  = sm1 + CC * W1T_STRIDE;       // [64]
    float* sh  = sc + CR;                     // [64]

    int tid = threadIdx.x;

    // W1 (64 x 256 row-major) transposed into smem: w1T[c][o]
    for (int i = tid; i < CR * CC; i += 128) {
        int o = i >> 8;
        int c = i & 255;
        w1T[c * W1T_STRIDE + o] = W1[i];
    }
    if (tid < CR) {
        float s = gamma[tid] * rsqrtf(var[tid] + 1e-5f);
        sc[tid] = s;
        sh[tid] = (b1[tid] - mean[tid]) * s + beta[tid];
    }
    __syncthreads();

    int s  = tid & 31;
    int oq = tid >> 5;                  // 0..3
    int qA = blockIdx.x * 64 + s;       // pixels qA and qA+32 (64 | NPIX, same batch)
    int b  = (blockIdx.x * 64) / NPIX;
    int hwA = qA - b * NPIX;
    const float* xp = x + (size_t)b * (CC * NPIX) + hwA;
    int o0 = oq * 16;

    unsigned long long accA[8], accB[8];
    #pragma unroll
    for (int m = 0; m < 8; m++) { accA[m] = 0ull; accB[m] = 0ull; }

    for (int c = 0; c < CC; c++) {
        float xa = xp[c * NPIX];
        float xb = xp[c * NPIX + 32];
        unsigned long long xa2 = f2u(xa, xa);
        unsigned long long xb2 = f2u(xb, xb);
        const float4* w4 = (const float4*)(w1T + c * W1T_STRIDE + o0);
        #pragma unroll
        for (int m = 0; m < 4; m++) {
            float4 w = w4[m];                       // broadcast LDS.128
            unsigned long long w01 = f2u(w.x, w.y);
            unsigned long long w23 = f2u(w.z, w.w);
            accA[2*m]   = ffma2(xa2, w01, accA[2*m]);
            accA[2*m+1] = ffma2(xa2, w23, accA[2*m+1]);
            accB[2*m]   = ffma2(xb2, w01, accB[2*m]);
            accB[2*m+1] = ffma2(xb2, w23, accB[2*m+1]);
        }
    }

    #pragma unroll
    for (int m = 0; m < 8; m++) {
        int o  = o0 + 2 * m;
        int c2 = oq * 8 + m;
        float2 vA = u2f(accA[m]);
        float a0 = fmaxf(vA.x * sc[o]   + sh[o],   0.f);
        float a1 = fmaxf(vA.y * sc[o+1] + sh[o+1], 0.f);
        t2_buf[(size_t)c2 * NQ + qA] = f2u(a0, a1);
        float2 vB = u2f(accB[m]);
        float b0 = fmaxf(vB.x * sc[o]   + sh[o],   0.f);
        float b1v = fmaxf(vB.y * sc[o+1] + sh[o+1], 0.f);
        t2_buf[(size_t)c2 * NQ + qA + 32] = f2u(b0, b1v);
    }
}

// =====================================================================
// Kernel 2 (fused): per-pixel kernel gen (GEMM2) + involution.
// Grid (7, 16, 4), 256 threads. CTA tile = 8 rows x 56 cols.
// Worker thread (tid<224) owns 2 vertically adjacent pixels
// (rows r0+2rl, r0+2rl+1). W2 broadcasts via LDS.128 serve both pixels.
// x tile in smem as channel pairs (c, c+8) -> float2, tap rows shared
// between the two pixels.
// =====================================================================
#define XT_W 62              // 56 + 6
#define XT_H 14              // 8  + 6
#define XT_CH (XT_H * XT_W)  // 868 float2 per channel-pair

extern "C" __global__ void __launch_bounds__(256)
k2_inv(const float* __restrict__ x, const float* __restrict__ W2,
       const float* __restrict__ b2, float* __restrict__ out)
{
    extern __shared__ float sm2[];
    float2* xs2 = (float2*)sm2;                  // [8][14][62] float2 = 13888 f
    float*  w2s = sm2 + 2 * 8 * XT_CH;           // [49][64] = 3136 f
    float*  b2s = w2s + 49 * CR;                 // [64]
    float*  ws  = b2s + 64;                      // [448][49] = 21952 f

    int tid = threadIdx.x;
    int r0  = blockIdx.x * 8;
    int g   = blockIdx.y;
    int b   = blockIdx.z;

    // ---- cooperative fills ----
    const float* xg = x + (size_t)((b * GG + g) * CGC) * NPIX;
    for (int i = tid; i < 8 * XT_CH; i += 256) {
        int cp  = i / XT_CH;
        int rem = i - cp * XT_CH;
        int ri  = rem / XT_W;
        int ci  = rem - ri * XT_W;
        int gr  = r0 - 3 + ri;
        int gc  = ci - 3;
        float v0 = 0.f, v1 = 0.f;
        if ((unsigned)gr < HH && (unsigned)gc < WW) {
            int off = gr * WW + gc;
            v0 = xg[cp * NPIX + off];
            v1 = xg[(cp + 8) * NPIX + off];
        }
        xs2[i] = make_float2(v0, v1);
    }
    for (int i = tid; i < 49 * CR; i += 256)
        w2s[i] = W2[(size_t)g * 49 * CR + i];
    if (tid < 49) b2s[tid] = b2[g * 49 + tid];

    // ---- per-thread t vectors for both pixels (registers) ----
    unsigned long long ttA[32], ttB[32];
    bool act = tid < 224;
    int rl = 0, cl = 0, qA = 0;
    if (act) {
        rl = tid / 56;
        cl = tid - rl * 56;
        int rA = r0 + 2 * rl;
        qA = b * NPIX + rA * WW + cl;
        #pragma unroll
        for (int c2 = 0; c2 < 32; c2++) {
            ttA[c2] = t2_buf[(size_t)c2 * NQ + qA];
            ttB[c2] = t2_buf[(size_t)c2 * NQ + qA + WW];
        }
    }
    __syncthreads();
    if (!act) return;

    // ---- kernel generation: w[p][k] = t[p] . W2[g,k] + b2, both pixels ----
    float* wsA = ws + tid * 49;
    float* wsB = ws + (224 + tid) * 49;
    for (int k = 0; k < 49; k++) {
        const float4* w4 = (const float4*)(w2s + (k << 6));
        unsigned long long aA0 = 0ull, aA1 = 0ull, aB0 = 0ull, aB1 = 0ull;
        #pragma unroll
        for (int m = 0; m < 16; m++) {
            float4 w = w4[m];                        // broadcast LDS.128
            unsigned long long w01 = f2u(w.x, w.y);
            unsigned long long w23 = f2u(w.z, w.w);
            aA0 = ffma2(ttA[2*m],   w01, aA0);
            aA1 = ffma2(ttA[2*m+1], w23, aA1);
            aB0 = ffma2(ttB[2*m],   w01, aB0);
            aB1 = ffma2(ttB[2*m+1], w23, aB1);
        }
        float bias = b2s[k];
        float2 uA0 = u2f(aA0), uA1 = u2f(aA1);
        wsA[k] = uA0.x + uA0.y + uA1.x + uA1.y + bias;
        float2 uB0 = u2f(aB0), uB1 = u2f(aB1);
        wsB[k] = uB0.x + uB0.y + uB1.x + uB1.y + bias;
    }

    // ---- involution: both pixels share the 8-row window ----
    unsigned long long oA[8], oB[8];
    #pragma unroll
    for (int cp = 0; cp < 8; cp++) { oA[cp] = 0ull; oB[cp] = 0ull; }

    // xs2 row for window-row t of this thread: (cp*14 + 2rl + t), col cl+j
    const float2* xb0 = xs2 + (2 * rl) * XT_W + cl;

    // t = 0: pixel A only (tap row 0)
    {
        #pragma unroll
        for (int j = 0; j < KK; j++) {
            float wa = wsA[j];
            unsigned long long wa2 = f2u(wa, wa);
            #pragma unroll
            for (int cp = 0; cp < 8; cp++) {
                unsigned long long xv =
                    *(const unsigned long long*)(xb0 + cp * XT_CH + j);
                oA[cp] = ffma2(xv, wa2, oA[cp]);
            }
        }
    }
    // t = 1..6: both pixels
    for (int t = 1; t <= 6; t++) {
        const float2* xbt = xb0 + t * XT_W;
        const float* wra = wsA + t * KK;
        const float* wrb = wsB + (t - 1) * KK;
        #pragma unroll
        for (int j = 0; j < KK; j++) {
            float wa = wra[j];
            float wb = wrb[j];
            unsigned long long wa2 = f2u(wa, wa);
            unsigned long long wb2 = f2u(wb, wb);
            #pragma unroll
            for (int cp = 0; cp < 8; cp++) {
                unsigned long long xv =
                    *(const unsigned long long*)(xbt + cp * XT_CH + j);
                oA[cp] = ffma2(xv, wa2, oA[cp]);
                oB[cp] = ffma2(xv, wb2, oB[cp]);
            }
        }
    }
    // t = 7: pixel B only (tap row 6)
    {
        const float2* xbt = xb0 + 7 * XT_W;
        #pragma unroll
        for (int j = 0; j < KK; j++) {
            float wb = wsB[42 + j];
            unsigned long long wb2 = f2u(wb, wb);
            #pragma unroll
            for (int cp = 0; cp < 8; cp++) {
                unsigned long long xv =
                    *(const unsigned long long*)(xbt + cp * XT_CH + j);
                oB[cp] = ffma2(xv, wb2, oB[cp]);
            }
        }
    }

    // ---- store: channel pair (cp, cp+8), rows rA and rA+1 ----
    int rA = r0 + 2 * rl;
    float* op = out + (size_t)(b * CC + g * CGC) * NPIX + rA * WW + cl;
    #pragma unroll
    for (int cp = 0; cp < 8; cp++) {
        float2 vA = u2f(oA[cp]);
        float2 vB = u2f(oB[cp]);
        op[cp * NPIX]            = vA.x;
        op[(cp + 8) * NPIX]      = vA.y;
        op[cp * NPIX + WW]       = vB.x;
        op[(cp + 8) * NPIX + WW] = vB.y;
    }
}

// =====================================================================
// Launch
// =====================================================================
extern "C" void kernel_launch(void* const* d_in, const int* in_sizes, int n_in,
                              void* d_out, int out_size) {
    const float* x     = (const float*)d_in[0];
    const float* W1    = (const float*)d_in[1];
    const float* b1    = (const float*)d_in[2];
    const float* gamma = (const float*)d_in[3];
    const float* beta  = (const float*)d_in[4];
    const float* mean  = (const float*)d_in[5];
    const float* var   = (const float*)d_in[6];
    const float* W2    = (const float*)d_in[7];
    const float* b2    = (const float*)d_in[8];
    float* out = (float*)d_out;

    const int smem1 = (CC * W1T_STRIDE + 2 * CR) * sizeof(float);               // ~68.5 KB
    const int smem2 = (2 * 8 * XT_CH + 49 * CR + 64 + 448 * 49) * sizeof(float); // ~152.5 KB

    (void)cudaFuncSetAttribute(k1_gen_t, cudaFuncAttributeMaxDynamicSharedMemorySize, smem1);
    (void)cudaFuncSetAttribute(k2_inv,   cudaFuncAttributeMaxDynamicSharedMemorySize, smem2);

    k1_gen_t<<<NQ / 64, 128, smem1>>>(x, W1, b1, gamma, beta, mean, var);
    k2_inv<<<dim3(HH / 8, GG, BB), 256, smem2>>>(x, W2, b2, out);
}